// round 6
// baseline (speedup 1.0000x reference)
#include <cuda_runtime.h>
#include <math.h>

#define NMB  4
#define CNUM 17
#define HNUM 8
#define BNUM 8
#define SLEN 512
#define DDIM 64
#define TI   64          // rows per block
#define JT   128         // j chunk per class pass
#define KSTR 68          // Ks row stride (floats): conflict-free, 16B-aligned rows
#define USTRD 68         // U row stride

// Premixed W1_^T: [C][h][n][m]  (transposed so a W column is contiguous)
__device__ float g_W[CNUM * HNUM * DDIM * DDIM];

// ---- packed f32x2 helpers ----
union F4U   { float4 f4; unsigned long long u[2]; };
union U64F2 { unsigned long long u; float2 f; };

__device__ __forceinline__ void ffma2(unsigned long long& d,
                                      unsigned long long a,
                                      unsigned long long b) {
    asm("fma.rn.f32x2 %0, %1, %2, %0;" : "+l"(d) : "l"(a), "l"(b));
}
__device__ __forceinline__ float hadd2(unsigned long long a) {
    U64F2 x; x.u = a; return x.f.x + x.f.y;
}

// ---------------- Kernel 1: W^T[c,h][n][m] = sum_B softmax(alpha1)[c,B,h] * W1[B,h][m][n]
__global__ void wmix_kernel(const float* __restrict__ W1,
                            const float* __restrict__ alpha1) {
    int c = blockIdx.x;   // 0..16
    int h = blockIdx.y;   // 0..7
    float a[NMB];
#pragma unroll
    for (int B = 0; B < NMB; B++) a[B] = alpha1[(c * NMB + B) * HNUM + h];
    float mx = fmaxf(fmaxf(a[0], a[1]), fmaxf(a[2], a[3]));
    float w[NMB], s = 0.f;
#pragma unroll
    for (int B = 0; B < NMB; B++) { w[B] = __expf(a[B] - mx); s += w[B]; }
    float inv = 1.f / s;
#pragma unroll
    for (int B = 0; B < NMB; B++) w[B] *= inv;

    float* dst = g_W + (c * HNUM + h) * DDIM * DDIM;
    const float* src = W1 + h * DDIM * DDIM;
    for (int e = threadIdx.x; e < DDIM * DDIM; e += blockDim.x) {
        int m = e >> 6, nn = e & 63;
        float v = 0.f;
#pragma unroll
        for (int B = 0; B < NMB; B++) v += w[B] * src[B * HNUM * DDIM * DDIM + e];
        dst[nn * DDIM + m] = v;   // transposed store
    }
}

// ---------------- Kernel 2: fused scores ----------------
// shared layout (bytes):
#define OFF_QS   0                           // 16384
#define OFF_U    16384                       // 64*68*4 = 17408
#define OFF_KS   (16384 + 17408)             // 128*68*4 = 34816
#define OFF_INT  (OFF_KS + 34816)
// ints: bj_all[512], jperm[512], jcnt[8], joff[8], jpos[8], rcnt[8], rlist[256]
#define SMEM_BYTES (OFF_INT + (512 + 512 + 8 + 8 + 8 + 8 + 256) * 4)

__global__ __launch_bounds__(256, 2)
void mb_scores_kernel(const float* __restrict__ q,
                      const float* __restrict__ k,
                      const int*   __restrict__ bseq,
                      float* __restrict__ out) {
    extern __shared__ unsigned char smraw[];
    float* Qs = (float*)(smraw + OFF_QS);
    float* Us = (float*)(smraw + OFF_U);
    float* Ks = (float*)(smraw + OFF_KS);
    int*   bj_all = (int*)(smraw + OFF_INT);
    int*   jperm  = bj_all + 512;
    int*   jcnt   = jperm + 512;
    int*   joff   = jcnt + 8;
    int*   jpos   = joff + 8;
    int*   rcnt   = jpos + 8;
    int*   rlist  = rcnt + 8;

    const int tid = threadIdx.x;
    const int it  = blockIdx.x;
    const int h   = blockIdx.y;
    const int b   = blockIdx.z;
    const int i0  = it * TI;

    const float* qbase = q + ((size_t)(b * HNUM + h) * SLEN + i0) * DDIM;
    const float* kbase = k + ((size_t)(b * HNUM + h) * SLEN) * DDIM;

    // load Q tile (64x64) as float4
    for (int t = tid; t < TI * DDIM / 4; t += 256)
        ((float4*)Qs)[t] = ((const float4*)qbase)[t];
    // load b_seq row
    for (int t = tid; t < SLEN; t += 256) bj_all[t] = bseq[b * SLEN + t];
    if (tid < 8) { jcnt[tid] = 0; rcnt[tid] = 0; }
    __syncthreads();

    // column class histogram
    for (int t = tid; t < SLEN; t += 256) atomicAdd(&jcnt[bj_all[t]], 1);
    __syncthreads();
    if (tid == 0) {
        int s = 0;
        for (int t = 0; t < 5; t++) { joff[t] = s; jpos[t] = s; s += jcnt[t]; }
    }
    __syncthreads();
    // column permutation grouped by class
    for (int t = tid; t < SLEN; t += 256) {
        int c = bj_all[t];
        int p = atomicAdd(&jpos[c], 1);
        jperm[p] = t;
    }
    // row lists grouped by bi value 1..4
    for (int t = tid; t < TI; t += 256) {
        int c = bj_all[i0 + t];
        if (c > 0) { int p = atomicAdd(&rcnt[c - 1], 1); rlist[(c - 1) * 64 + p] = t; }
    }
    __syncthreads();

    const int n = tid & 63;
    const int g = tid >> 6;   // 0..3

    // ---------------- Phase A0: slot0 for all 64 rows (4 rows / iter) ----
    {
        const F4U* Wt = (const F4U*)(g_W + (size_t)h * DDIM * DDIM + n * DDIM); // c=0
        unsigned long long wp[32];
#pragma unroll
        for (int qd = 0; qd < 16; qd++) {
            F4U w4 = Wt[qd];
            wp[2 * qd] = w4.u[0]; wp[2 * qd + 1] = w4.u[1];
        }
#pragma unroll
        for (int r = 0; r < 16; r += 4) {
            int i = g * 16 + r;
            const F4U* q0 = (const F4U*)(Qs + (i + 0) * DDIM);
            const F4U* q1 = (const F4U*)(Qs + (i + 1) * DDIM);
            const F4U* q2 = (const F4U*)(Qs + (i + 2) * DDIM);
            const F4U* q3 = (const F4U*)(Qs + (i + 3) * DDIM);
            unsigned long long a0 = 0, a1 = 0, b0 = 0, b1 = 0;
            unsigned long long c0 = 0, c1 = 0, d0 = 0, d1 = 0;
#pragma unroll
            for (int mb = 0; mb < 16; mb++) {
                F4U v0 = q0[mb], v1 = q1[mb], v2 = q2[mb], v3 = q3[mb];
                ffma2(a0, v0.u[0], wp[2 * mb]); ffma2(a1, v0.u[1], wp[2 * mb + 1]);
                ffma2(b0, v1.u[0], wp[2 * mb]); ffma2(b1, v1.u[1], wp[2 * mb + 1]);
                ffma2(c0, v2.u[0], wp[2 * mb]); ffma2(c1, v2.u[1], wp[2 * mb + 1]);
                ffma2(d0, v3.u[0], wp[2 * mb]); ffma2(d1, v3.u[1], wp[2 * mb + 1]);
            }
            Us[(i + 0) * USTRD + n] = hadd2(a0) + hadd2(a1);
            Us[(i + 1) * USTRD + n] = hadd2(b0) + hadd2(b1);
            Us[(i + 2) * USTRD + n] = hadd2(c0) + hadd2(c1);
            Us[(i + 3) * USTRD + n] = hadd2(d0) + hadd2(d1);
        }
    }

    // ---------------- class passes ----------------
    const int tx = tid & 31, ty = tid >> 5;   // 32 x 8
    float* outbase = out + ((size_t)(b * HNUM + h) * SLEN + i0) * SLEN;

    int prevClass = 0;
    for (int t = 0; t < 5; t++) {
        int nt  = jcnt[t];
        int off = joff[t];
        if (nt == 0) continue;

        // class transition: recompute U rows with bi>0 for class t
        if (t > 0 && t != prevClass) {
            __syncthreads();   // prior pass readers done
            int v   = g + 1;              // this group's bi value
            int cnt = rcnt[v - 1];
            if (cnt > 0) {
                int cc = 4 * (v - 1) + t;  // 1..16
                const F4U* Wt = (const F4U*)(g_W + (size_t)(cc * HNUM + h) * DDIM * DDIM + n * DDIM);
                unsigned long long wp[32];
#pragma unroll
                for (int qd = 0; qd < 16; qd++) {
                    F4U w4 = Wt[qd];
                    wp[2 * qd] = w4.u[0]; wp[2 * qd + 1] = w4.u[1];
                }
                int r = 0;
                for (; r + 3 < cnt; r += 4) {
                    int ia = rlist[(v - 1) * 64 + r];
                    int ib = rlist[(v - 1) * 64 + r + 1];
                    int ic = rlist[(v - 1) * 64 + r + 2];
                    int id = rlist[(v - 1) * 64 + r + 3];
                    const F4U* q0 = (const F4U*)(Qs + ia * DDIM);
                    const F4U* q1 = (const F4U*)(Qs + ib * DDIM);
                    const F4U* q2 = (const F4U*)(Qs + ic * DDIM);
                    const F4U* q3 = (const F4U*)(Qs + id * DDIM);
                    unsigned long long a0 = 0, a1 = 0, b0 = 0, b1 = 0;
                    unsigned long long c0 = 0, c1 = 0, d0 = 0, d1 = 0;
#pragma unroll
                    for (int mb = 0; mb < 16; mb++) {
                        F4U v0 = q0[mb], v1 = q1[mb], v2 = q2[mb], v3 = q3[mb];
                        ffma2(a0, v0.u[0], wp[2 * mb]); ffma2(a1, v0.u[1], wp[2 * mb + 1]);
                        ffma2(b0, v1.u[0], wp[2 * mb]); ffma2(b1, v1.u[1], wp[2 * mb + 1]);
                        ffma2(c0, v2.u[0], wp[2 * mb]); ffma2(c1, v2.u[1], wp[2 * mb + 1]);
                        ffma2(d0, v3.u[0], wp[2 * mb]); ffma2(d1, v3.u[1], wp[2 * mb + 1]);
                    }
                    Us[ia * USTRD + n] = hadd2(a0) + hadd2(a1);
                    Us[ib * USTRD + n] = hadd2(b0) + hadd2(b1);
                    Us[ic * USTRD + n] = hadd2(c0) + hadd2(c1);
                    Us[id * USTRD + n] = hadd2(d0) + hadd2(d1);
                }
                for (; r < cnt; r++) {
                    int ia = rlist[(v - 1) * 64 + r];
                    const F4U* q0 = (const F4U*)(Qs + ia * DDIM);
                    unsigned long long a0 = 0, a1 = 0;
#pragma unroll
                    for (int mb = 0; mb < 16; mb++) {
                        F4U v0 = q0[mb];
                        ffma2(a0, v0.u[0], wp[2 * mb]);
                        ffma2(a1, v0.u[1], wp[2 * mb + 1]);
                    }
                    Us[ia * USTRD + n] = hadd2(a0) + hadd2(a1);
                }
            }
            prevClass = t;
        }

        for (int j0 = 0; j0 < nt; j0 += JT) {
            int chunk = nt - j0; if (chunk > JT) chunk = JT;
            __syncthreads();   // Ks reuse safety + U visibility
            // gather K chunk rows (coalesced 256B rows)
            for (int x = tid; x < JT * 16; x += 256) {
                int r = x >> 4, mb = x & 15;
                float4 v;
                if (r < chunk) v = ((const float4*)(kbase + (size_t)jperm[off + j0 + r] * DDIM))[mb];
                else           v = make_float4(0.f, 0.f, 0.f, 0.f);
                *(float4*)(Ks + r * KSTR + mb * 4) = v;
            }
            __syncthreads();

            // register tile: 8 rows (stride 8) x 4 cols (stride 32), packed acc
            unsigned long long acc[8][4];
#pragma unroll
            for (int ii = 0; ii < 8; ii++)
#pragma unroll
                for (int jj = 0; jj < 4; jj++) acc[ii][jj] = 0ull;

#pragma unroll
            for (int mb = 0; mb < 16; mb++) {
                F4U kv[4];
#pragma unroll
                for (int jj = 0; jj < 4; jj++)
                    kv[jj].f4 = *(const float4*)(Ks + (tx + jj * 32) * KSTR + mb * 4);
#pragma unroll
                for (int ii = 0; ii < 8; ii++) {
                    F4U av;
                    av.f4 = *(const float4*)(Us + (ty + ii * 8) * USTRD + mb * 4);
#pragma unroll
                    for (int jj = 0; jj < 4; jj++) {
                        ffma2(acc[ii][jj], av.u[0], kv[jj].u[0]);
                        ffma2(acc[ii][jj], av.u[1], kv[jj].u[1]);
                    }
                }
            }
            // scattered stores (L2 write-coalesced)
#pragma unroll
            for (int jj = 0; jj < 4; jj++) {
                int jc = tx + jj * 32;
                if (j0 + jc < nt) {
                    int jp = jperm[off + j0 + jc];
#pragma unroll
                    for (int ii = 0; ii < 8; ii++)
                        outbase[(size_t)(ty + ii * 8) * SLEN + jp] = hadd2(acc[ii][jj]);
                }
            }
        }
    }
}

// ---------------- launch ----------------
extern "C" void kernel_launch(void* const* d_in, const int* in_sizes, int n_in,
                              void* d_out, int out_size) {
    const float* q      = (const float*)d_in[0];
    const float* kk     = (const float*)d_in[1];
    const int*   bseq   = (const int*)  d_in[2];
    const float* W1     = (const float*)d_in[3];
    const float* alpha1 = (const float*)d_in[4];
    float* out = (float*)d_out;

    cudaFuncSetAttribute(mb_scores_kernel,
                         cudaFuncAttributeMaxDynamicSharedMemorySize, SMEM_BYTES);

    dim3 g1(CNUM, HNUM);
    wmix_kernel<<<g1, 256>>>(W1, alpha1);

    dim3 g2(SLEN / TI, HNUM, BNUM);   // 512 blocks
    mb_scores_kernel<<<g2, 256, SMEM_BYTES>>>(q, kk, bseq, out);
}

// round 7
// speedup vs baseline: 1.0574x; 1.0574x over previous
#include <cuda_runtime.h>
#include <math.h>
#include <stdint.h>

#define NMB  4
#define CNUM 17
#define HNUM 8
#define BNUM 8
#define SLEN 512
#define DDIM 64
#define TI   64          // rows per block
#define JT   128         // j chunk per class pass
#define KSTR 68          // Ks row stride (floats): conflict-free, 16B-aligned rows
#define USTRD 68         // U row stride
#define MAXCH 12

// Premixed W1_^T: [C][h][n][m]  (transposed so a W column is contiguous)
__device__ float g_W[CNUM * HNUM * DDIM * DDIM];

// ---- packed f32x2 helpers ----
union F4U   { float4 f4; unsigned long long u[2]; };
union U64F2 { unsigned long long u; float2 f; };

__device__ __forceinline__ void ffma2(unsigned long long& d,
                                      unsigned long long a,
                                      unsigned long long b) {
    asm("fma.rn.f32x2 %0, %1, %2, %0;" : "+l"(d) : "l"(a), "l"(b));
}
__device__ __forceinline__ float hadd2(unsigned long long a) {
    U64F2 x; x.u = a; return x.f.x + x.f.y;
}

#define CP_COMMIT() asm volatile("cp.async.commit_group;")
#define CP_WAIT0()  asm volatile("cp.async.wait_group 0;" ::: "memory")

// ---------------- Kernel 1: W^T[c,h][n][m] = sum_B softmax(alpha1)[c,B,h] * W1[B,h][m][n]
__global__ void wmix_kernel(const float* __restrict__ W1,
                            const float* __restrict__ alpha1) {
    int c = blockIdx.x;   // 0..16
    int h = blockIdx.y;   // 0..7
    float a[NMB];
#pragma unroll
    for (int B = 0; B < NMB; B++) a[B] = alpha1[(c * NMB + B) * HNUM + h];
    float mx = fmaxf(fmaxf(a[0], a[1]), fmaxf(a[2], a[3]));
    float w[NMB], s = 0.f;
#pragma unroll
    for (int B = 0; B < NMB; B++) { w[B] = __expf(a[B] - mx); s += w[B]; }
    float inv = 1.f / s;
#pragma unroll
    for (int B = 0; B < NMB; B++) w[B] *= inv;

    float* dst = g_W + (c * HNUM + h) * DDIM * DDIM;
    const float* src = W1 + h * DDIM * DDIM;
    for (int e = threadIdx.x; e < DDIM * DDIM; e += blockDim.x) {
        int m = e >> 6, nn = e & 63;
        float v = 0.f;
#pragma unroll
        for (int B = 0; B < NMB; B++) v += w[B] * src[B * HNUM * DDIM * DDIM + e];
        dst[nn * DDIM + m] = v;   // transposed store
    }
}

// ---------------- Kernel 2: fused scores ----------------
// shared layout (bytes):
#define OFF_QS   0                           // 16384
#define OFF_U    16384                       // 64*68*4 = 17408
#define OFF_KS   (16384 + 17408)             // 2 * 128*68*4 = 69632
#define OFF_INT  (OFF_KS + 2 * JT * KSTR * 4)
// ints: bj_all[512] jperm[512] jcnt[8] joff[8] jpos[8] rcnt[8] rlist[256]
//       cls[12] coff[12] clen[12] nch[4]
#define NINTS (512 + 512 + 8 + 8 + 8 + 8 + 256 + MAXCH * 3 + 4)
#define SMEM_BYTES (OFF_INT + NINTS * 4)

__global__ __launch_bounds__(256, 2)
void mb_scores_kernel(const float* __restrict__ q,
                      const float* __restrict__ k,
                      const int*   __restrict__ bseq,
                      float* __restrict__ out) {
    extern __shared__ unsigned char smraw[];
    float* Qs = (float*)(smraw + OFF_QS);
    float* Us = (float*)(smraw + OFF_U);
    float* Ks = (float*)(smraw + OFF_KS);     // 2 buffers of JT*KSTR
    int* bj_all = (int*)(smraw + OFF_INT);
    int* jperm  = bj_all + 512;
    int* jcnt   = jperm + 512;
    int* joff   = jcnt + 8;
    int* jpos   = joff + 8;
    int* rcnt   = jpos + 8;
    int* rlist  = rcnt + 8;
    int* cls    = rlist + 256;
    int* coff   = cls + MAXCH;
    int* clen   = coff + MAXCH;
    int* nchS   = clen + MAXCH;

    const int tid = threadIdx.x;
    const int it  = blockIdx.x;
    const int h   = blockIdx.y;
    const int b   = blockIdx.z;
    const int i0  = it * TI;

    const float* qbase = q + ((size_t)(b * HNUM + h) * SLEN + i0) * DDIM;
    const float* kbase = k + ((size_t)(b * HNUM + h) * SLEN) * DDIM;

    // load Q tile (64x64) as float4
    for (int t = tid; t < TI * DDIM / 4; t += 256)
        ((float4*)Qs)[t] = ((const float4*)qbase)[t];
    for (int t = tid; t < SLEN; t += 256) bj_all[t] = bseq[b * SLEN + t];
    if (tid < 8) { jcnt[tid] = 0; rcnt[tid] = 0; }
    __syncthreads();

    for (int t = tid; t < SLEN; t += 256) atomicAdd(&jcnt[bj_all[t]], 1);
    __syncthreads();
    if (tid == 0) {
        int s = 0;
        for (int t = 0; t < 5; t++) { joff[t] = s; jpos[t] = s; s += jcnt[t]; }
        int nc = 0;
        for (int t = 0; t < 5; t++) {
            int nt = jcnt[t], off = joff[t];
            for (int j0 = 0; j0 < nt; j0 += JT) {
                cls[nc] = t; coff[nc] = off + j0;
                clen[nc] = (nt - j0 < JT) ? (nt - j0) : JT;
                nc++;
            }
        }
        nchS[0] = nc;
    }
    __syncthreads();
    for (int t = tid; t < SLEN; t += 256) {
        int c = bj_all[t];
        int p = atomicAdd(&jpos[c], 1);
        jperm[p] = t;
    }
    for (int t = tid; t < TI; t += 256) {
        int c = bj_all[i0 + t];
        if (c > 0) { int p = atomicAdd(&rcnt[c - 1], 1); rlist[(c - 1) * 64 + p] = t; }
    }
    __syncthreads();

    const int ncls = nchS[0];
    const int n = tid & 63;
    const int g = tid >> 6;   // 0..3

    // ---- prologue: issue async gather of chunk 0 into buffer 0 ----
    {
        int len = clen[0], off = coff[0];
#pragma unroll
        for (int itr = 0; itr < 8; itr++) {
            int x = tid + itr * 256;
            int r = x >> 4, mb = x & 15;
            int rr = (r < len) ? r : (len - 1);
            const float* src = kbase + (size_t)jperm[off + rr] * DDIM + mb * 4;
            uint32_t daddr = (uint32_t)__cvta_generic_to_shared(Ks + r * KSTR + mb * 4);
            int sz = (r < len) ? 16 : 0;
            asm volatile("cp.async.ca.shared.global [%0], [%1], 16, %2;"
                         :: "r"(daddr), "l"(src), "r"(sz));
        }
        CP_COMMIT();
    }

    // ---- Phase A0: slot0 for all 64 rows (R2-style: 2 rows, 1 acc each) ----
    {
        const F4U* Wt = (const F4U*)(g_W + (size_t)h * DDIM * DDIM + n * DDIM); // c=0
        unsigned long long wp[32];
#pragma unroll
        for (int qd = 0; qd < 16; qd++) {
            F4U w4 = Wt[qd];
            wp[2 * qd] = w4.u[0]; wp[2 * qd + 1] = w4.u[1];
        }
        for (int r = 0; r < 16; r += 2) {
            int i = g * 16 + r;
            const F4U* qa = (const F4U*)(Qs + i * DDIM);
            const F4U* qb = (const F4U*)(Qs + (i + 1) * DDIM);
            unsigned long long a0 = 0, b0 = 0;
#pragma unroll
            for (int mb = 0; mb < 16; mb++) {
                F4U va = qa[mb], vb = qb[mb];
                ffma2(a0, va.u[0], wp[2 * mb]);
                ffma2(a0, va.u[1], wp[2 * mb + 1]);
                ffma2(b0, vb.u[0], wp[2 * mb]);
                ffma2(b0, vb.u[1], wp[2 * mb + 1]);
            }
            Us[i * USTRD + n]       = hadd2(a0);
            Us[(i + 1) * USTRD + n] = hadd2(b0);
        }
    }
    CP_WAIT0();
    __syncthreads();   // buffer 0 + U(slot0) ready

    const int tx = tid & 31, ty = tid >> 5;   // 32 x 8
    float* outbase = out + ((size_t)(b * HNUM + h) * SLEN + i0) * SLEN;

    int prevClass = 0;
    for (int c = 0; c < ncls; c++) {
        const int t = cls[c];
        const float* Kbuf = Ks + (c & 1) * (JT * KSTR);

        // (1) issue prefetch of chunk c+1 into the other buffer
        if (c + 1 < ncls) {
            int len = clen[c + 1], off = coff[c + 1];
            float* dst = Ks + ((c + 1) & 1) * (JT * KSTR);
#pragma unroll
            for (int itr = 0; itr < 8; itr++) {
                int x = tid + itr * 256;
                int r = x >> 4, mb = x & 15;
                int rr = (r < len) ? r : (len - 1);
                const float* src = kbase + (size_t)jperm[off + rr] * DDIM + mb * 4;
                uint32_t daddr = (uint32_t)__cvta_generic_to_shared(dst + r * KSTR + mb * 4);
                int sz = (r < len) ? 16 : 0;
                asm volatile("cp.async.ca.shared.global [%0], [%1], 16, %2;"
                             :: "r"(daddr), "l"(src), "r"(sz));
            }
            CP_COMMIT();
        }

        // (2) class transition: recompute U rows with bi>0 for class t
        if (t != prevClass && t > 0) {
            __syncthreads();   // previous chunk's compute (reads Us) is done
            int v = g + 1;
            int cnt = rcnt[v - 1];
            if (cnt > 0) {
                int cc = 4 * (v - 1) + t;
                const F4U* Wt = (const F4U*)(g_W + (size_t)(cc * HNUM + h) * DDIM * DDIM + n * DDIM);
                unsigned long long wp[32];
#pragma unroll
                for (int qd = 0; qd < 16; qd++) {
                    F4U w4 = Wt[qd];
                    wp[2 * qd] = w4.u[0]; wp[2 * qd + 1] = w4.u[1];
                }
                int r = 0;
                for (; r + 1 < cnt; r += 2) {
                    int ia = rlist[(v - 1) * 64 + r];
                    int ib = rlist[(v - 1) * 64 + r + 1];
                    const F4U* qa = (const F4U*)(Qs + ia * DDIM);
                    const F4U* qb = (const F4U*)(Qs + ib * DDIM);
                    unsigned long long a0 = 0, b0 = 0;
#pragma unroll
                    for (int mb = 0; mb < 16; mb++) {
                        F4U va = qa[mb], vb = qb[mb];
                        ffma2(a0, va.u[0], wp[2 * mb]);
                        ffma2(a0, va.u[1], wp[2 * mb + 1]);
                        ffma2(b0, vb.u[0], wp[2 * mb]);
                        ffma2(b0, vb.u[1], wp[2 * mb + 1]);
                    }
                    Us[ia * USTRD + n] = hadd2(a0);
                    Us[ib * USTRD + n] = hadd2(b0);
                }
                if (r < cnt) {
                    int ia = rlist[(v - 1) * 64 + r];
                    const F4U* qa = (const F4U*)(Qs + ia * DDIM);
                    unsigned long long a0 = 0;
#pragma unroll
                    for (int mb = 0; mb < 16; mb++) {
                        F4U va = qa[mb];
                        ffma2(a0, va.u[0], wp[2 * mb]);
                        ffma2(a0, va.u[1], wp[2 * mb + 1]);
                    }
                    Us[ia * USTRD + n] = hadd2(a0);
                }
            }
            __syncthreads();   // U visible
            prevClass = t;
        }

        // (3) compute chunk c: 8 rows x 4 cols packed acc per thread
        {
            unsigned long long acc[8][4];
#pragma unroll
            for (int ii = 0; ii < 8; ii++)
#pragma unroll
                for (int jj = 0; jj < 4; jj++) acc[ii][jj] = 0ull;

#pragma unroll
            for (int mb = 0; mb < 16; mb++) {
                F4U kv[4];
#pragma unroll
                for (int jj = 0; jj < 4; jj++)
                    kv[jj].f4 = *(const float4*)(Kbuf + (tx + jj * 32) * KSTR + mb * 4);
#pragma unroll
                for (int ii = 0; ii < 8; ii++) {
                    F4U av;
                    av.f4 = *(const float4*)(Us + (ty + ii * 8) * USTRD + mb * 4);
#pragma unroll
                    for (int jj = 0; jj < 4; jj++) {
                        ffma2(acc[ii][jj], av.u[0], kv[jj].u[0]);
                        ffma2(acc[ii][jj], av.u[1], kv[jj].u[1]);
                    }
                }
            }
            int chunk = clen[c], off = coff[c];
#pragma unroll
            for (int jj = 0; jj < 4; jj++) {
                int jc = tx + jj * 32;
                if (jc < chunk) {
                    int jp = jperm[off + jc];
#pragma unroll
                    for (int ii = 0; ii < 8; ii++)
                        outbase[(size_t)(ty + ii * 8) * SLEN + jp] = hadd2(acc[ii][jj]);
                }
            }
        }

        // (4) next buffer ready + all threads done with this chunk
        CP_WAIT0();
        __syncthreads();
    }
}

// ---------------- launch ----------------
extern "C" void kernel_launch(void* const* d_in, const int* in_sizes, int n_in,
                              void* d_out, int out_size) {
    const float* q      = (const float*)d_in[0];
    const float* kk     = (const float*)d_in[1];
    const int*   bseq   = (const int*)  d_in[2];
    const float* W1     = (const float*)d_in[3];
    const float* alpha1 = (const float*)d_in[4];
    float* out = (float*)d_out;

    cudaFuncSetAttribute(mb_scores_kernel,
                         cudaFuncAttributeMaxDynamicSharedMemorySize, SMEM_BYTES);

    dim3 g1(CNUM, HNUM);
    wmix_kernel<<<g1, 256>>>(W1, alpha1);

    dim3 g2(SLEN / TI, HNUM, BNUM);   // 512 blocks
    mb_scores_kernel<<<g2, 256, SMEM_BYTES>>>(q, kk, bseq, out);
}

// round 9
// speedup vs baseline: 1.3986x; 1.3226x over previous
#include <cuda_runtime.h>
#include <cuda_bf16.h>
#include <stdint.h>

#define NMB  4
#define CNUM 17
#define HNUM 8
#define BNUM 8
#define SLEN 512
#define DDIM 64
#define TI   64
#define JT   128
#define MAXCH 12
#define AST  200   // A' row stride (bf16): 400B -> conflict-free ldmatrix
#define BST  200   // B' row stride (bf16)

// Premixed W1_: [C][h][m][n]  (n-major: lane-coalesced reads, the R2-good layout)
__device__ float g_W[CNUM * HNUM * DDIM * DDIM];

// ---- packed f32x2 helpers (phase A) ----
union F4U   { float4 f4; unsigned long long u[2]; };
union U64F2 { unsigned long long u; float2 f; };
__device__ __forceinline__ void ffma2(unsigned long long& d,
                                      unsigned long long a,
                                      unsigned long long b) {
    asm("fma.rn.f32x2 %0, %1, %2, %0;" : "+l"(d) : "l"(a), "l"(b));
}
__device__ __forceinline__ unsigned long long pack2(float x, float y) {
    unsigned long long r;
    asm("mov.b64 %0, {%1, %2};" : "=l"(r) : "f"(x), "f"(y));
    return r;
}
__device__ __forceinline__ float hadd2(unsigned long long a) {
    U64F2 x; x.u = a; return x.f.x + x.f.y;
}

// ---- HMMA helpers (base-arch: ldmatrix + mma.sync bf16) ----
#define LDSM4(r, a) \
    asm volatile("ldmatrix.sync.aligned.m8n8.x4.shared.b16 {%0,%1,%2,%3}, [%4];" \
        : "=r"((r)[0]), "=r"((r)[1]), "=r"((r)[2]), "=r"((r)[3]) : "r"(a))

#define MMA16816(d, a, b0v, b1v) \
    asm volatile("mma.sync.aligned.m16n8k16.row.col.f32.bf16.bf16.f32 " \
        "{%0,%1,%2,%3}, {%4,%5,%6,%7}, {%8,%9}, {%0,%1,%2,%3};" \
        : "+f"((d)[0]), "+f"((d)[1]), "+f"((d)[2]), "+f"((d)[3]) \
        : "r"((a)[0]), "r"((a)[1]), "r"((a)[2]), "r"((a)[3]), "r"(b0v), "r"(b1v))

// ---------------- Kernel 1: premix W ----------------
__global__ void wmix_kernel(const float* __restrict__ W1,
                            const float* __restrict__ alpha1) {
    int c = blockIdx.x, h = blockIdx.y;
    float a[NMB];
#pragma unroll
    for (int B = 0; B < NMB; B++) a[B] = alpha1[(c * NMB + B) * HNUM + h];
    float mx = fmaxf(fmaxf(a[0], a[1]), fmaxf(a[2], a[3]));
    float w[NMB], s = 0.f;
#pragma unroll
    for (int B = 0; B < NMB; B++) { w[B] = __expf(a[B] - mx); s += w[B]; }
    float inv = 1.f / s;
#pragma unroll
    for (int B = 0; B < NMB; B++) w[B] *= inv;
    float* dst = g_W + (c * HNUM + h) * DDIM * DDIM;
    const float* src = W1 + h * DDIM * DDIM;
    for (int e = threadIdx.x; e < DDIM * DDIM; e += blockDim.x) {
        float v = 0.f;
#pragma unroll
        for (int B = 0; B < NMB; B++) v += w[B] * src[B * HNUM * DDIM * DDIM + e];
        dst[e] = v;
    }
}

// ---------------- shared layout (bytes) ----------------
#define OFF_Q    0                     // 64*64*4   = 16384
#define OFF_A    16384                 // 64*AST*2  = 25600
#define OFF_B    (16384 + 25600)       // 128*BST*2 = 51200
#define OFF_INT  (OFF_B + 51200)
// ints: bj_all[512] jperm[512] rlist[256] jcnt8 joff8 jpos8 rcnt8 cls12 coff12 clen12 nch4
#define NINTS (512 + 512 + 256 + 8 + 8 + 8 + 8 + MAXCH * 3 + 4)
#define SMEM_BYTES (OFF_INT + NINTS * 4)

// phase-A row: U fp32 -> bf16 hi/lo into A' slices [H | H | L]
__device__ __forceinline__ void urow(const float* Qs, unsigned char* Ab,
                                     const unsigned long long* wp, int i, int n) {
    const F4U* qa = (const F4U*)(Qs + i * DDIM);
    unsigned long long a0 = 0, a1 = 0;
#pragma unroll
    for (int mb = 0; mb < 16; mb++) {
        F4U v = qa[mb];
        ffma2(a0, v.u[0], wp[2 * mb]);
        ffma2(a1, v.u[1], wp[2 * mb + 1]);
    }
    float u = hadd2(a0) + hadd2(a1);
    __nv_bfloat16 hi = __float2bfloat16(u);
    __nv_bfloat16 lo = __float2bfloat16(u - __bfloat162float(hi));
    uint32_t o = (uint32_t)(i * AST + n) * 2;
    *(__nv_bfloat16*)(Ab + o)       = hi;   // slice 0: UH
    *(__nv_bfloat16*)(Ab + o + 128) = hi;   // slice 1: UH (cols +64)
    *(__nv_bfloat16*)(Ab + o + 256) = lo;   // slice 2: UL (cols +128)
}

__device__ __forceinline__ void cvt4(float4 v, uint32_t& hw0, uint32_t& hw1,
                                     uint32_t& lw0, uint32_t& lw1) {
    __nv_bfloat162 h0 = __floats2bfloat162_rn(v.x, v.y);
    __nv_bfloat162 h1 = __floats2bfloat162_rn(v.z, v.w);
    float lx = v.x - __bfloat162float(h0.x);
    float ly = v.y - __bfloat162float(h0.y);
    float lz = v.z - __bfloat162float(h1.x);
    float lw = v.w - __bfloat162float(h1.y);
    __nv_bfloat162 l0 = __floats2bfloat162_rn(lx, ly);
    __nv_bfloat162 l1 = __floats2bfloat162_rn(lz, lw);
    hw0 = *(uint32_t*)&h0; hw1 = *(uint32_t*)&h1;
    lw0 = *(uint32_t*)&l0; lw1 = *(uint32_t*)&l1;
}

__global__ __launch_bounds__(256, 2)
void mb_scores_kernel(const float* __restrict__ q,
                      const float* __restrict__ k,
                      const int*   __restrict__ bseq,
                      float* __restrict__ out) {
    extern __shared__ unsigned char smraw[];
    float* Qs = (float*)(smraw + OFF_Q);
    unsigned char* Ab = smraw + OFF_A;
    unsigned char* Bb = smraw + OFF_B;
    int* bj_all = (int*)(smraw + OFF_INT);
    int* jperm  = bj_all + 512;
    int* rlist  = jperm + 512;
    int* jcnt   = rlist + 256;
    int* joff   = jcnt + 8;
    int* jpos   = joff + 8;
    int* rcnt   = jpos + 8;
    int* cls    = rcnt + 8;
    int* coff   = cls + MAXCH;
    int* clen   = coff + MAXCH;
    int* nchS   = clen + MAXCH;

    const int tid = threadIdx.x;
    const int wid = tid >> 5;
    const int lid = tid & 31;
    const int it  = blockIdx.x;
    const int h   = blockIdx.y;
    const int b   = blockIdx.z;
    const int i0  = it * TI;

    const float* qbase = q + ((size_t)(b * HNUM + h) * SLEN + i0) * DDIM;
    const float* kbase = k + ((size_t)(b * HNUM + h) * SLEN) * DDIM;

    for (int t = tid; t < TI * DDIM / 4; t += 256)
        ((float4*)Qs)[t] = ((const float4*)qbase)[t];
    for (int t = tid; t < SLEN; t += 256) bj_all[t] = bseq[b * SLEN + t];
    if (tid < 8) { jcnt[tid] = 0; rcnt[tid] = 0; }
    __syncthreads();

    for (int t = tid; t < SLEN; t += 256) atomicAdd(&jcnt[bj_all[t]], 1);
    __syncthreads();
    if (tid == 0) {
        int s = 0;
        for (int t = 0; t < 5; t++) { joff[t] = s; jpos[t] = s; s += jcnt[t]; }
        int nc = 0;
        for (int t = 0; t < 5; t++) {
            int nt = jcnt[t], off = joff[t];
            for (int j0 = 0; j0 < nt; j0 += JT) {
                cls[nc] = t; coff[nc] = off + j0;
                clen[nc] = (nt - j0 < JT) ? (nt - j0) : JT;
                nc++;
            }
        }
        nchS[0] = nc;
    }
    __syncthreads();
    for (int t = tid; t < SLEN; t += 256) {
        int c = bj_all[t];
        int p = atomicAdd(&jpos[c], 1);
        jperm[p] = t;
    }
    for (int t = tid; t < TI; t += 256) {
        int c = bj_all[i0 + t];
        if (c > 0) { int p = atomicAdd(&rcnt[c - 1], 1); rlist[(c - 1) * 64 + p] = t; }
    }
    __syncthreads();

    const int ncls = nchS[0];
    const int n = tid & 63;
    const int g = tid >> 6;   // 0..3

    // ---- Phase A0: slot0 for all 64 rows (R2-style, coalesced W reads) ----
    {
        const float* W0 = g_W + (size_t)h * DDIM * DDIM + n;   // c=0
        unsigned long long wp[32];
#pragma unroll
        for (int m2 = 0; m2 < 32; m2++)
            wp[m2] = pack2(W0[(2 * m2) * DDIM], W0[(2 * m2 + 1) * DDIM]);
        for (int r = 0; r < 16; r += 2) {
            urow(Qs, Ab, wp, g * 16 + r, n);
            urow(Qs, Ab, wp, g * 16 + r + 1, n);
        }
    }

    // ---- per-warp ldmatrix lane addressing ----
    const uint32_t smem_base = (uint32_t)__cvta_generic_to_shared(smraw);
    const int wr = (wid >> 2) * 32;        // warp row base (0/32)
    const int wc = (wid & 3) * 32;         // warp col base (0/32/64/96)
    // A: lane -> row (wr + mt*16 + (lid&15)), col (ks*16 + (lid&16 ? 8:0))
    uint32_t aAddr0 = smem_base + OFF_A +
        (uint32_t)(((wr + (lid & 15)) * AST + ((lid & 16) ? 8 : 0)) * 2);
    uint32_t aAddr1 = aAddr0 + 16 * AST * 2;
    // B: lane -> row (wc + nt*16 + (lid&7) + (lid&16 ? 8:0)), col (ks*16 + (lid&8 ? 8:0))
    uint32_t bAddr0 = smem_base + OFF_B +
        (uint32_t)(((wc + (lid & 7) + ((lid & 16) ? 8 : 0)) * BST + ((lid & 8) ? 8 : 0)) * 2);
    uint32_t bAddr1 = bAddr0 + 16 * BST * 2;

    float* outbase = out + ((size_t)(b * HNUM + h) * SLEN + i0) * SLEN;

    int prevClass = 0;
    for (int c = 0; c < ncls; c++) {
        const int t   = cls[c];
        const int len = clen[c];
        const int off = coff[c];

        // class transition: rewrite A' rows with bi>0 for class t
        if (t > 0 && t != prevClass) {
            int v = g + 1;
            int cnt = rcnt[v - 1];
            if (cnt > 0) {
                int cc = 4 * (v - 1) + t;
                const float* Wc = g_W + (size_t)(cc * HNUM + h) * DDIM * DDIM + n;
                unsigned long long wp[32];
#pragma unroll
                for (int m2 = 0; m2 < 32; m2++)
                    wp[m2] = pack2(Wc[(2 * m2) * DDIM], Wc[(2 * m2 + 1) * DDIM]);
                int r = 0;
                for (; r + 1 < cnt; r += 2) {
                    urow(Qs, Ab, wp, rlist[(v - 1) * 64 + r], n);
                    urow(Qs, Ab, wp, rlist[(v - 1) * 64 + r + 1], n);
                }
                if (r < cnt) urow(Qs, Ab, wp, rlist[(v - 1) * 64 + r], n);
            }
            prevClass = t;
        }

        // ---- convert K chunk -> B' slices [KH | KL | KH] ----
        {
            int j2 = tid >> 1, half = tid & 1;
            if (j2 < len) {
                int jp = jperm[off + j2];
                const float4* src = (const float4*)(kbase + (size_t)jp * DDIM + half * 32);
#pragma unroll
                for (int qd = 0; qd < 8; qd++) {
                    float4 v = src[qd];
                    uint32_t hw0, hw1, lw0, lw1;
                    cvt4(v, hw0, hw1, lw0, lw1);
                    uint32_t byt = (uint32_t)(j2 * BST + half * 32 + qd * 4) * 2;
                    *(uint32_t*)(Bb + byt)       = hw0;
                    *(uint32_t*)(Bb + byt + 4)   = hw1;
                    *(uint32_t*)(Bb + byt + 128) = lw0;   // cols +64
                    *(uint32_t*)(Bb + byt + 132) = lw1;
                    *(uint32_t*)(Bb + byt + 256) = hw0;   // cols +128
                    *(uint32_t*)(Bb + byt + 260) = hw1;
                }
            }
        }
        __syncthreads();   // A' + B' visible

        // ---- HMMA mainloop: K' = 192 (12 k16-steps) ----
        float d[2][4][4];
#pragma unroll
        for (int mt = 0; mt < 2; mt++)
#pragma unroll
            for (int n8 = 0; n8 < 4; n8++)
#pragma unroll
                for (int e = 0; e < 4; e++) d[mt][n8][e] = 0.f;

#pragma unroll
        for (int ks = 0; ks < 12; ks++) {
            uint32_t a0[4], a1[4], b0[4], b1[4];
            LDSM4(a0, aAddr0 + ks * 32);
            LDSM4(a1, aAddr1 + ks * 32);
            LDSM4(b0, bAddr0 + ks * 32);
            LDSM4(b1, bAddr1 + ks * 32);
            MMA16816(d[0][0], a0, b0[0], b0[1]);
            MMA16816(d[0][1], a0, b0[2], b0[3]);
            MMA16816(d[0][2], a0, b1[0], b1[1]);
            MMA16816(d[0][3], a0, b1[2], b1[3]);
            MMA16816(d[1][0], a1, b0[0], b0[1]);
            MMA16816(d[1][1], a1, b0[2], b0[3]);
            MMA16816(d[1][2], a1, b1[0], b1[1]);
            MMA16816(d[1][3], a1, b1[2], b1[3]);
        }

        // ---- epilogue: fragments -> scattered global stores via jperm ----
        {
            int rbase = wr + (lid >> 2);
            int cb    = wc + (lid & 3) * 2;
#pragma unroll
            for (int n8 = 0; n8 < 4; n8++) {
                int col = cb + n8 * 8;
                if (col < len) {
                    int jp = jperm[off + col];
#pragma unroll
                    for (int mt = 0; mt < 2; mt++) {
                        int row = rbase + mt * 16;
                        outbase[(size_t)row * SLEN + jp]       = d[mt][n8][0];
                        outbase[(size_t)(row + 8) * SLEN + jp] = d[mt][n8][2];
                    }
                }
                if (col + 1 < len) {
                    int jp = jperm[off + col + 1];
#pragma unroll
                    for (int mt = 0; mt < 2; mt++) {
                        int row = rbase + mt * 16;
                        outbase[(size_t)row * SLEN + jp]       = d[mt][n8][1];
                        outbase[(size_t)(row + 8) * SLEN + jp] = d[mt][n8][3];
                    }
                }
            }
        }
        __syncthreads();   // all reads of A'/B' done before next chunk overwrites
    }
}

// ---------------- launch ----------------
extern "C" void kernel_launch(void* const* d_in, const int* in_sizes, int n_in,
                              void* d_out, int out_size) {
    const float* q      = (const float*)d_in[0];
    const float* kk     = (const float*)d_in[1];
    const int*   bseq   = (const int*)  d_in[2];
    const float* W1     = (const float*)d_in[3];
    const float* alpha1 = (const float*)d_in[4];
    float* out = (float*)d_out;

    cudaFuncSetAttribute(mb_scores_kernel,
                         cudaFuncAttributeMaxDynamicSharedMemorySize, SMEM_BYTES);

    dim3 g1(CNUM, HNUM);
    wmix_kernel<<<g1, 256>>>(W1, alpha1);

    dim3 g2(SLEN / TI, HNUM, BNUM);   // 512 blocks
    mb_scores_kernel<<<g2, 256, SMEM_BYTES>>>(q, kk, bseq, out);
}

// round 10
// speedup vs baseline: 1.4459x; 1.0339x over previous
#include <cuda_runtime.h>
#include <cuda_bf16.h>
#include <stdint.h>

#define NMB  4
#define CNUM 17
#define HNUM 8
#define BNUM 8
#define SLEN 512
#define DDIM 64
#define TI   64
#define JT   128
#define MAXCH 12
#define AST  136   // A' row stride (bf16): 272B -> conflict-free ldmatrix
#define BST  136   // B' row stride (bf16)

// Premixed W1_: [C][h][m][n]  (n-major: lane-coalesced reads)
__device__ float g_W[CNUM * HNUM * DDIM * DDIM];

// ---- packed f32x2 helpers (phase A) ----
union F4U   { float4 f4; unsigned long long u[2]; };
union U64F2 { unsigned long long u; float2 f; };
__device__ __forceinline__ void ffma2(unsigned long long& d,
                                      unsigned long long a,
                                      unsigned long long b) {
    asm("fma.rn.f32x2 %0, %1, %2, %0;" : "+l"(d) : "l"(a), "l"(b));
}
__device__ __forceinline__ unsigned long long pack2(float x, float y) {
    unsigned long long r;
    asm("mov.b64 %0, {%1, %2};" : "=l"(r) : "f"(x), "f"(y));
    return r;
}
__device__ __forceinline__ float hadd2(unsigned long long a) {
    U64F2 x; x.u = a; return x.f.x + x.f.y;
}

// ---- HMMA helpers (base-arch: ldmatrix + mma.sync bf16) ----
#define LDSM4(r, a) \
    asm volatile("ldmatrix.sync.aligned.m8n8.x4.shared.b16 {%0,%1,%2,%3}, [%4];" \
        : "=r"((r)[0]), "=r"((r)[1]), "=r"((r)[2]), "=r"((r)[3]) : "r"(a))

#define MMA16816(d, a, b0v, b1v) \
    asm volatile("mma.sync.aligned.m16n8k16.row.col.f32.bf16.bf16.f32 " \
        "{%0,%1,%2,%3}, {%4,%5,%6,%7}, {%8,%9}, {%0,%1,%2,%3};" \
        : "+f"((d)[0]), "+f"((d)[1]), "+f"((d)[2]), "+f"((d)[3]) \
        : "r"((a)[0]), "r"((a)[1]), "r"((a)[2]), "r"((a)[3]), "r"(b0v), "r"(b1v))

// ---------------- Kernel 1: premix W ----------------
__global__ void wmix_kernel(const float* __restrict__ W1,
                            const float* __restrict__ alpha1) {
    int c = blockIdx.x, h = blockIdx.y;
    float a[NMB];
#pragma unroll
    for (int B = 0; B < NMB; B++) a[B] = alpha1[(c * NMB + B) * HNUM + h];
    float mx = fmaxf(fmaxf(a[0], a[1]), fmaxf(a[2], a[3]));
    float w[NMB], s = 0.f;
#pragma unroll
    for (int B = 0; B < NMB; B++) { w[B] = __expf(a[B] - mx); s += w[B]; }
    float inv = 1.f / s;
#pragma unroll
    for (int B = 0; B < NMB; B++) w[B] *= inv;
    float* dst = g_W + (c * HNUM + h) * DDIM * DDIM;
    const float* src = W1 + h * DDIM * DDIM;
    for (int e = threadIdx.x; e < DDIM * DDIM; e += blockDim.x) {
        float v = 0.f;
#pragma unroll
        for (int B = 0; B < NMB; B++) v += w[B] * src[B * HNUM * DDIM * DDIM + e];
        dst[e] = v;
    }
}

// ---------------- shared layout (bytes) ----------------
#define OFF_Q    0                     // 64*64*4   = 16384
#define OFF_A    16384                 // 64*AST*2  = 17408
#define OFF_B    (16384 + 17408)       // 128*BST*2 = 34816
#define OFF_INT  (OFF_B + 34816)
// ints: bj_all[512] jperm[512] rlist[256] jcnt8 joff8 jpos8 rcnt8 cls12 coff12 clen12 nch4
#define NINTS (512 + 512 + 256 + 8 + 8 + 8 + 8 + MAXCH * 3 + 4)
#define SMEM_BYTES (OFF_INT + NINTS * 4)

// phase-A row: U fp32 -> bf16 hi/lo into A' slices [UH | UL]
__device__ __forceinline__ void urow(const float* Qs, unsigned char* Ab,
                                     const unsigned long long* wp, int i, int n) {
    const F4U* qa = (const F4U*)(Qs + i * DDIM);
    unsigned long long a0 = 0, a1 = 0;
#pragma unroll
    for (int mb = 0; mb < 16; mb++) {
        F4U v = qa[mb];
        ffma2(a0, v.u[0], wp[2 * mb]);
        ffma2(a1, v.u[1], wp[2 * mb + 1]);
    }
    float u = hadd2(a0) + hadd2(a1);
    __nv_bfloat16 hi = __float2bfloat16(u);
    __nv_bfloat16 lo = __float2bfloat16(u - __bfloat162float(hi));
    uint32_t o = (uint32_t)(i * AST + n) * 2;
    *(__nv_bfloat16*)(Ab + o)       = hi;   // slice 0: UH
    *(__nv_bfloat16*)(Ab + o + 128) = lo;   // slice 1: UL (cols +64)
}

__device__ __forceinline__ void cvt4(float4 v, uint32_t& hw0, uint32_t& hw1,
                                     uint32_t& lw0, uint32_t& lw1) {
    __nv_bfloat162 h0 = __floats2bfloat162_rn(v.x, v.y);
    __nv_bfloat162 h1 = __floats2bfloat162_rn(v.z, v.w);
    float lx = v.x - __bfloat162float(h0.x);
    float ly = v.y - __bfloat162float(h0.y);
    float lz = v.z - __bfloat162float(h1.x);
    float lw = v.w - __bfloat162float(h1.y);
    __nv_bfloat162 l0 = __floats2bfloat162_rn(lx, ly);
    __nv_bfloat162 l1 = __floats2bfloat162_rn(lz, lw);
    hw0 = *(uint32_t*)&h0; hw1 = *(uint32_t*)&h1;
    lw0 = *(uint32_t*)&l0; lw1 = *(uint32_t*)&l1;
}

__global__ __launch_bounds__(256, 2)
void mb_scores_kernel(const float* __restrict__ q,
                      const float* __restrict__ k,
                      const int*   __restrict__ bseq,
                      float* __restrict__ out) {
    extern __shared__ unsigned char smraw[];
    float* Qs = (float*)(smraw + OFF_Q);
    unsigned char* Ab = smraw + OFF_A;
    unsigned char* Bb = smraw + OFF_B;
    int* bj_all = (int*)(smraw + OFF_INT);
    int* jperm  = bj_all + 512;
    int* rlist  = jperm + 512;
    int* jcnt   = rlist + 256;
    int* joff   = jcnt + 8;
    int* jpos   = joff + 8;
    int* rcnt   = jpos + 8;
    int* cls    = rcnt + 8;
    int* coff   = cls + MAXCH;
    int* clen   = coff + MAXCH;
    int* nchS   = clen + MAXCH;

    const int tid = threadIdx.x;
    const int wid = tid >> 5;
    const int lid = tid & 31;
    const int it  = blockIdx.x;
    const int h   = blockIdx.y;
    const int b   = blockIdx.z;
    const int i0  = it * TI;

    const float* qbase = q + ((size_t)(b * HNUM + h) * SLEN + i0) * DDIM;
    const float* kbase = k + ((size_t)(b * HNUM + h) * SLEN) * DDIM;

    for (int t = tid; t < TI * DDIM / 4; t += 256)
        ((float4*)Qs)[t] = ((const float4*)qbase)[t];
    for (int t = tid; t < SLEN; t += 256) bj_all[t] = bseq[b * SLEN + t];
    if (tid < 8) { jcnt[tid] = 0; rcnt[tid] = 0; }
    __syncthreads();

    for (int t = tid; t < SLEN; t += 256) atomicAdd(&jcnt[bj_all[t]], 1);
    __syncthreads();
    if (tid == 0) {
        int s = 0;
        for (int t = 0; t < 5; t++) { joff[t] = s; jpos[t] = s; s += jcnt[t]; }
        int nc = 0;
        for (int t = 0; t < 5; t++) {
            int nt = jcnt[t], off = joff[t];
            for (int j0 = 0; j0 < nt; j0 += JT) {
                cls[nc] = t; coff[nc] = off + j0;
                clen[nc] = (nt - j0 < JT) ? (nt - j0) : JT;
                nc++;
            }
        }
        nchS[0] = nc;
    }
    __syncthreads();
    for (int t = tid; t < SLEN; t += 256) {
        int c = bj_all[t];
        int p = atomicAdd(&jpos[c], 1);
        jperm[p] = t;
    }
    for (int t = tid; t < TI; t += 256) {
        int c = bj_all[i0 + t];
        if (c > 0) { int p = atomicAdd(&rcnt[c - 1], 1); rlist[(c - 1) * 64 + p] = t; }
    }
    __syncthreads();

    const int ncls = nchS[0];
    const int n = tid & 63;
    const int g = tid >> 6;   // 0..3

    // ---- Phase A0: slot0 for all 64 rows (coalesced W reads) ----
    {
        const float* W0 = g_W + (size_t)h * DDIM * DDIM + n;   // c=0
        unsigned long long wp[32];
#pragma unroll
        for (int m2 = 0; m2 < 32; m2++)
            wp[m2] = pack2(W0[(2 * m2) * DDIM], W0[(2 * m2 + 1) * DDIM]);
        for (int r = 0; r < 16; r += 2) {
            urow(Qs, Ab, wp, g * 16 + r, n);
            urow(Qs, Ab, wp, g * 16 + r + 1, n);
        }
    }
    __syncthreads();   // A0 complete before any cross-group rewrite

    // ---- per-warp ldmatrix lane addressing ----
    const uint32_t smem_base = (uint32_t)__cvta_generic_to_shared(smraw);
    const int wr = (wid >> 2) * 32;        // warp row base (0/32)
    const int wc = (wid & 3) * 32;         // warp col base (0/32/64/96)
    uint32_t aAddr0 = smem_base + OFF_A +
        (uint32_t)(((wr + (lid & 15)) * AST + ((lid & 16) ? 8 : 0)) * 2);
    uint32_t aAddr1 = aAddr0 + 16 * AST * 2;
    uint32_t bAddr0 = smem_base + OFF_B +
        (uint32_t)(((wc + (lid & 7) + ((lid & 16) ? 8 : 0)) * BST + ((lid & 8) ? 8 : 0)) * 2);
    uint32_t bAddr1 = bAddr0 + 16 * BST * 2;

    float* outbase = out + ((size_t)(b * HNUM + h) * SLEN + i0) * SLEN;

    int prevClass = 0;
    for (int c = 0; c < ncls; c++) {
        const int t   = cls[c];
        const int len = clen[c];
        const int off = coff[c];

        // class transition: rewrite A' rows with bi>0 for class t
        if (t > 0 && t != prevClass) {
            int v = g + 1;
            int cnt = rcnt[v - 1];
            if (cnt > 0) {
                int cc = 4 * (v - 1) + t;
                const float* Wc = g_W + (size_t)(cc * HNUM + h) * DDIM * DDIM + n;
                unsigned long long wp[32];
#pragma unroll
                for (int m2 = 0; m2 < 32; m2++)
                    wp[m2] = pack2(Wc[(2 * m2) * DDIM], Wc[(2 * m2 + 1) * DDIM]);
                int r = 0;
                for (; r + 1 < cnt; r += 2) {
                    urow(Qs, Ab, wp, rlist[(v - 1) * 64 + r], n);
                    urow(Qs, Ab, wp, rlist[(v - 1) * 64 + r + 1], n);
                }
                if (r < cnt) urow(Qs, Ab, wp, rlist[(v - 1) * 64 + r], n);
            }
            prevClass = t;
        }

        // ---- convert K chunk -> B' slices [KH | KL] ----
        {
            int j2 = tid >> 1, half = tid & 1;
            if (j2 < len) {
                int jp = jperm[off + j2];
                const float4* src = (const float4*)(kbase + (size_t)jp * DDIM + half * 32);
#pragma unroll
                for (int qd = 0; qd < 8; qd++) {
                    float4 v = src[qd];
                    uint32_t hw0, hw1, lw0, lw1;
                    cvt4(v, hw0, hw1, lw0, lw1);
                    uint32_t byt = (uint32_t)(j2 * BST + half * 32 + qd * 4) * 2;
                    *(uint32_t*)(Bb + byt)       = hw0;
                    *(uint32_t*)(Bb + byt + 4)   = hw1;
                    *(uint32_t*)(Bb + byt + 128) = lw0;   // KL slice (cols +64)
                    *(uint32_t*)(Bb + byt + 132) = lw1;
                }
            }
        }
        __syncthreads();   // A' + B' visible

        // ---- HMMA mainloop: 3 terms (UH·KH, UH·KL, UL·KH) x 4 k-steps ----
        float d[2][4][4];
#pragma unroll
        for (int mt = 0; mt < 2; mt++)
#pragma unroll
            for (int n8 = 0; n8 < 4; n8++)
#pragma unroll
                for (int e = 0; e < 4; e++) d[mt][n8][e] = 0.f;

#pragma unroll
        for (int s = 0; s < 3; s++) {
            const uint32_t aOff = (s == 2) ? 128u : 0u;   // UL slice
            const uint32_t bOff = (s == 1) ? 128u : 0u;   // KL slice
#pragma unroll
            for (int ks = 0; ks < 4; ks++) {
                uint32_t a0[4], a1[4], b0[4], b1[4];
                LDSM4(a0, aAddr0 + aOff + ks * 32);
                LDSM4(a1, aAddr1 + aOff + ks * 32);
                LDSM4(b0, bAddr0 + bOff + ks * 32);
                LDSM4(b1, bAddr1 + bOff + ks * 32);
                MMA16816(d[0][0], a0, b0[0], b0[1]);
                MMA16816(d[0][1], a0, b0[2], b0[3]);
                MMA16816(d[0][2], a0, b1[0], b1[1]);
                MMA16816(d[0][3], a0, b1[2], b1[3]);
                MMA16816(d[1][0], a1, b0[0], b0[1]);
                MMA16816(d[1][1], a1, b0[2], b0[3]);
                MMA16816(d[1][2], a1, b1[0], b1[1]);
                MMA16816(d[1][3], a1, b1[2], b1[3]);
            }
        }

        // ---- epilogue: fragments -> scattered global stores via jperm ----
        {
            int rbase = wr + (lid >> 2);
            int cb    = wc + (lid & 3) * 2;
#pragma unroll
            for (int n8 = 0; n8 < 4; n8++) {
                int col = cb + n8 * 8;
                if (col < len) {
                    int jp = jperm[off + col];
#pragma unroll
                    for (int mt = 0; mt < 2; mt++) {
                        int row = rbase + mt * 16;
                        outbase[(size_t)row * SLEN + jp]       = d[mt][n8][0];
                        outbase[(size_t)(row + 8) * SLEN + jp] = d[mt][n8][2];
                    }
                }
                if (col + 1 < len) {
                    int jp = jperm[off + col + 1];
#pragma unroll
                    for (int mt = 0; mt < 2; mt++) {
                        int row = rbase + mt * 16;
                        outbase[(size_t)row * SLEN + jp]       = d[mt][n8][1];
                        outbase[(size_t)(row + 8) * SLEN + jp] = d[mt][n8][3];
                    }
                }
            }
        }
        __syncthreads();   // all reads of A'/B' done before next chunk overwrites
    }
}

// ---------------- launch ----------------
extern "C" void kernel_launch(void* const* d_in, const int* in_sizes, int n_in,
                              void* d_out, int out_size) {
    const float* q      = (const float*)d_in[0];
    const float* kk     = (const float*)d_in[1];
    const int*   bseq   = (const int*)  d_in[2];
    const float* W1     = (const float*)d_in[3];
    const float* alpha1 = (const float*)d_in[4];
    float* out = (float*)d_out;

    cudaFuncSetAttribute(mb_scores_kernel,
                         cudaFuncAttributeMaxDynamicSharedMemorySize, SMEM_BYTES);

    dim3 g1(CNUM, HNUM);
    wmix_kernel<<<g1, 256>>>(W1, alpha1);

    dim3 g2(SLEN / TI, HNUM, BNUM);   // 512 blocks
    mb_scores_kernel<<<g2, 256, SMEM_BYTES>>>(q, kk, bseq, out);
}